// round 2
// baseline (speedup 1.0000x reference)
#include <cuda_runtime.h>
#include <math.h>

// Problem constants (fixed by the reference setup)
#define T   2048
#define Hd  1024
#define Id  512
#define Ed  16
#define TK  6
#define TD  (T * TK)    // 12288 dispatched rows (always exactly 6 per token)
#define I2  1024        // 2*I (shared expert intermediate)

#define BK 16

// ---------------- scratch (static __device__, no allocations) ----------------
__device__ __align__(16) float g_act [TD * Id];   // routed silu(g)*u activations
__device__ __align__(16) float g_ybuf[TD * Hd];   // per-(t,k) weighted down output
__device__ __align__(16) float g_sact[T  * I2];   // shared-expert activations
__device__ float g_weight_tk[TD];
__device__ float g_row_w[TD];
__device__ int   g_expert_idx[TD];
__device__ int   g_row_token[TD];
__device__ int   g_pos[TD];        // (t*6+k) -> dispatch row p
__device__ int   g_counts[Ed];
__device__ int   g_offsets[Ed];
__device__ int   g_cursors[Ed];

// ---------------------------------------------------------------------------
__global__ void k_zero() {
    int i = threadIdx.x;
    if (i < Ed) g_counts[i] = 0;
}

// gating: sigmoid scores, top-6 (bias-corrected selection), normalized weights
__global__ void k_gate(const float* __restrict__ x,
                       const float* __restrict__ gw,
                       const float* __restrict__ gb) {
    int warp = threadIdx.x >> 5;
    int lane = threadIdx.x & 31;
    int t = blockIdx.x * 4 + warp;

    const float* xp = x + (size_t)t * Hd;
    float xr[32];
#pragma unroll
    for (int j = 0; j < 32; j++) xr[j] = xp[j * 32 + lane];

    __shared__ float ssc[4][Ed];
    for (int e = 0; e < Ed; e++) {
        const float* w = gw + (size_t)e * Hd;
        float s = 0.f;
#pragma unroll
        for (int j = 0; j < 32; j++) s += xr[j] * w[j * 32 + lane];
#pragma unroll
        for (int o = 16; o; o >>= 1) s += __shfl_xor_sync(0xffffffffu, s, o);
        if (lane == 0) ssc[warp][e] = 1.f / (1.f + expf(-s));
    }
    __syncwarp();

    if (lane == 0) {
        float sc[Ed], adj[Ed];
        for (int e = 0; e < Ed; e++) { sc[e] = ssc[warp][e]; adj[e] = sc[e] + gb[e]; }
        int   idx[TK];
        float w[TK];
        float sum = 0.f;
        for (int k = 0; k < TK; k++) {
            int   a  = 0;
            float mv = adj[0];
            for (int e = 1; e < Ed; e++) {     // strict > : first-occurrence max (jax tie-break)
                if (adj[e] > mv) { mv = adj[e]; a = e; }
            }
            idx[k] = a;
            w[k]   = sc[a];
            sum   += w[k];
            adj[a] = -INFINITY;
        }
        float inv = 1.f / (sum + 1e-20f);
        for (int k = 0; k < TK; k++) {
            g_expert_idx[t * TK + k] = idx[k];
            g_weight_tk[t * TK + k]  = w[k] * inv;
            atomicAdd(&g_counts[idx[k]], 1);
        }
    }
}

__global__ void k_scan() {
    if (threadIdx.x == 0) {
        int o = 0;
        for (int e = 0; e < Ed; e++) {
            g_offsets[e] = o;
            g_cursors[e] = o;
            o += g_counts[e];
        }
    }
}

__global__ void k_scatter() {
    int i = blockIdx.x * blockDim.x + threadIdx.x;
    if (i < TD) {
        int e = g_expert_idx[i];
        int p = atomicAdd(&g_cursors[e], 1);
        g_row_token[p] = i / TK;
        g_row_w[p]     = g_weight_tk[i];
        g_pos[i]       = p;
    }
}

// ---------------------------------------------------------------------------
// Dual-output GEMM (gate + up) with SiLU epilogue.
// BM=128, BN=64, BK=16, 256 threads, 8x4 microtile per matrix.
// gather != 0 : A rows gathered via g_row_token (routed path, bounded by cnt).
template<int LDB>
__device__ __forceinline__ void gemm_gateup_body(
    const float* __restrict__ abase, int lda, int gather,
    int cnt, int off, int m0, int n0,
    const float* __restrict__ Bg, const float* __restrict__ Bu,
    float* __restrict__ dst, int ldd, int K)
{
    __shared__ float As [BK][128];
    __shared__ float Bgs[BK][64];
    __shared__ float Bus[BK][64];

    const int tid = threadIdx.x;

    // A loader: 2 chunks/thread; chunk c -> m = c&127, kq = c>>7 (float4 along k)
    const float* asrc[2];
#pragma unroll
    for (int i = 0; i < 2; i++) {
        int c = tid + i * 256;
        int m = c & 127, kq = c >> 7;
        int r = m0 + m;
        if (r < cnt) {
            int row = gather ? g_row_token[off + r] : r;
            asrc[i] = abase + (size_t)row * lda + kq * 4;
        } else asrc[i] = nullptr;
    }
    // B loader: 1 float4/thread/matrix: br = tid>>4, bc = (tid&15)*4
    const int br = tid >> 4, bc = (tid & 15) << 2;
    const float* bgp = Bg + (size_t)br * LDB + n0 + bc;
    const float* bup = Bu + (size_t)br * LDB + n0 + bc;

    const int tx = tid & 15;       // N: 16 x 4 = 64
    const int ty = tid >> 4;       // M: 16 x 8 = 128

    float accg[8][4] = {};
    float accu[8][4] = {};

    for (int k0 = 0; k0 < K; k0 += BK) {
#pragma unroll
        for (int i = 0; i < 2; i++) {
            int c = tid + i * 256;
            int m = c & 127, kq = c >> 7;
            float4 v = make_float4(0.f, 0.f, 0.f, 0.f);
            if (asrc[i]) v = *(const float4*)(asrc[i] + k0);
            As[kq * 4 + 0][m] = v.x; As[kq * 4 + 1][m] = v.y;
            As[kq * 4 + 2][m] = v.z; As[kq * 4 + 3][m] = v.w;
        }
        *(float4*)&Bgs[br][bc] = *(const float4*)(bgp + (size_t)k0 * LDB);
        *(float4*)&Bus[br][bc] = *(const float4*)(bup + (size_t)k0 * LDB);
        __syncthreads();
#pragma unroll
        for (int k = 0; k < BK; k++) {
            float4 a0 = *(float4*)&As[k][ty * 8];
            float4 a1 = *(float4*)&As[k][ty * 8 + 4];
            float  a[8] = {a0.x, a0.y, a0.z, a0.w, a1.x, a1.y, a1.z, a1.w};
            float4 bgv = *(float4*)&Bgs[k][tx * 4];
            float4 buv = *(float4*)&Bus[k][tx * 4];
            float bg[4] = {bgv.x, bgv.y, bgv.z, bgv.w};
            float bu[4] = {buv.x, buv.y, buv.z, buv.w};
#pragma unroll
            for (int i = 0; i < 8; i++)
#pragma unroll
                for (int j = 0; j < 4; j++) {
                    accg[i][j] += a[i] * bg[j];
                    accu[i][j] += a[i] * bu[j];
                }
        }
        __syncthreads();
    }
#pragma unroll
    for (int i = 0; i < 8; i++) {
        int r = m0 + ty * 8 + i;
        if (r < cnt) {
            float* d = dst + (size_t)(off + r) * ldd + n0 + tx * 4;
#pragma unroll
            for (int j = 0; j < 4; j++) {
                float g = accg[i][j], u = accu[i][j];
                d[j] = (g / (1.f + expf(-g))) * u;
            }
        }
    }
}

__global__ void __launch_bounds__(256, 2)
k_routed_gateup(const float* __restrict__ x,
                const float* __restrict__ wg,
                const float* __restrict__ wu) {
    const int e   = blockIdx.z;
    const int cnt = g_counts[e];
    const int m0  = blockIdx.y * 128;
    if (m0 >= cnt) return;
    gemm_gateup_body<Id>(x, Hd, 1, cnt, g_offsets[e], m0, blockIdx.x * 64,
                         wg + (size_t)e * Hd * Id, wu + (size_t)e * Hd * Id,
                         g_act, Id, Hd);
}

__global__ void __launch_bounds__(256, 2)
k_shared_gateup(const float* __restrict__ x,
                const float* __restrict__ wsg,
                const float* __restrict__ wsu) {
    gemm_gateup_body<I2>(x, Hd, 0, T, 0, blockIdx.y * 128, blockIdx.x * 64,
                         wsg, wsu, g_sact, I2, Hd);
}

// ---------------------------------------------------------------------------
// Single-output GEMM: BM=128, BN=128, BK=16, 256 threads, 8x8 microtile.
// mode 0: routed down (epilogue * g_row_w -> g_ybuf)
// mode 1: shared down + combine (epilogue + sum_k ybuf -> out)
template<int MODE>
__device__ __forceinline__ void gemm_down_body(
    const float* __restrict__ abase, int lda,
    int cnt, int off, int m0, int n0,
    const float* __restrict__ B, int ldb, int K,
    float* __restrict__ dst, int ldd)
{
    __shared__ float As[BK][128];
    __shared__ float Bs[BK][128];

    const int tid = threadIdx.x;

    const float* asrc[2];
#pragma unroll
    for (int i = 0; i < 2; i++) {
        int c = tid + i * 256;
        int m = c & 127, kq = c >> 7;
        int r = m0 + m;
        asrc[i] = (r < cnt) ? abase + (size_t)(off + r) * lda + kq * 4 : nullptr;
    }
    // B loader: 2 float4/thread: br = c>>5 (32 float4/row), bc = (c&31)*4
    const float* bsrc[2];
    int bro[2], bco[2];
#pragma unroll
    for (int i = 0; i < 2; i++) {
        int c = tid + i * 256;
        bro[i] = c >> 5; bco[i] = (c & 31) << 2;
        bsrc[i] = B + (size_t)bro[i] * ldb + n0 + bco[i];
    }

    const int tx = tid & 15;   // N: 16 x 8 = 128
    const int ty = tid >> 4;   // M: 16 x 8 = 128

    float acc[8][8] = {};

    for (int k0 = 0; k0 < K; k0 += BK) {
#pragma unroll
        for (int i = 0; i < 2; i++) {
            int c = tid + i * 256;
            int m = c & 127, kq = c >> 7;
            float4 v = make_float4(0.f, 0.f, 0.f, 0.f);
            if (asrc[i]) v = *(const float4*)(asrc[i] + k0);
            As[kq * 4 + 0][m] = v.x; As[kq * 4 + 1][m] = v.y;
            As[kq * 4 + 2][m] = v.z; As[kq * 4 + 3][m] = v.w;
        }
#pragma unroll
        for (int i = 0; i < 2; i++)
            *(float4*)&Bs[bro[i]][bco[i]] = *(const float4*)(bsrc[i] + (size_t)k0 * ldb);
        __syncthreads();
#pragma unroll
        for (int k = 0; k < BK; k++) {
            float4 a0 = *(float4*)&As[k][ty * 8];
            float4 a1 = *(float4*)&As[k][ty * 8 + 4];
            float  a[8] = {a0.x, a0.y, a0.z, a0.w, a1.x, a1.y, a1.z, a1.w};
            float4 b0 = *(float4*)&Bs[k][tx * 8];
            float4 b1 = *(float4*)&Bs[k][tx * 8 + 4];
            float  b[8] = {b0.x, b0.y, b0.z, b0.w, b1.x, b1.y, b1.z, b1.w};
#pragma unroll
            for (int i = 0; i < 8; i++)
#pragma unroll
                for (int j = 0; j < 8; j++) acc[i][j] += a[i] * b[j];
        }
        __syncthreads();
    }

#pragma unroll
    for (int i = 0; i < 8; i++) {
        int r = m0 + ty * 8 + i;
        if (r < cnt) {
            float* d = dst + (size_t)(off + r) * ldd + n0 + tx * 8;
            if (MODE == 0) {
                float w = g_row_w[off + r];
#pragma unroll
                for (int j = 0; j < 8; j++) d[j] = acc[i][j] * w;
            } else {
                float add[8] = {};
#pragma unroll
                for (int k = 0; k < TK; k++) {
                    const float* yb = g_ybuf + (size_t)g_pos[r * TK + k] * Hd + n0 + tx * 8;
#pragma unroll
                    for (int j = 0; j < 8; j++) add[j] += yb[j];
                }
#pragma unroll
                for (int j = 0; j < 8; j++) d[j] = acc[i][j] + add[j];
            }
        }
    }
}

__global__ void __launch_bounds__(256, 2)
k_routed_down(const float* __restrict__ wd) {
    const int e   = blockIdx.z;
    const int cnt = g_counts[e];
    const int m0  = blockIdx.y * 128;
    if (m0 >= cnt) return;
    gemm_down_body<0>(g_act, Id, cnt, g_offsets[e], m0, blockIdx.x * 128,
                      wd + (size_t)e * Id * Hd, Hd, Id, g_ybuf, Hd);
}

__global__ void __launch_bounds__(256, 2)
k_final(const float* __restrict__ wsd, float* __restrict__ out) {
    gemm_down_body<1>(g_sact, I2, T, 0, blockIdx.y * 128, blockIdx.x * 128,
                      wsd, Hd, I2, out, Hd);
}

// ---------------------------------------------------------------------------
extern "C" void kernel_launch(void* const* d_in, const int* in_sizes, int n_in,
                              void* d_out, int out_size) {
    const float* x    = (const float*)d_in[0];  // [1,2048,1024]
    const float* gw   = (const float*)d_in[1];  // [16,1024]
    const float* gb   = (const float*)d_in[2];  // [16]
    const float* wg   = (const float*)d_in[3];  // [16,1024,512]
    const float* wu   = (const float*)d_in[4];  // [16,1024,512]
    const float* wd   = (const float*)d_in[5];  // [16,512,1024]
    const float* wsg  = (const float*)d_in[6];  // [1024,1024]
    const float* wsu  = (const float*)d_in[7];  // [1024,1024]
    const float* wsd  = (const float*)d_in[8];  // [1024,1024]
    float* out = (float*)d_out;

    k_zero<<<1, 32>>>();
    k_gate<<<T / 4, 128>>>(x, gw, gb);
    k_scan<<<1, 32>>>();
    k_scatter<<<(TD + 255) / 256, 256>>>();

    k_routed_gateup<<<dim3(Id / 64, T / 128, Ed), 256>>>(x, wg, wu);
    k_routed_down  <<<dim3(Hd / 128, T / 128, Ed), 256>>>(wd);

    k_shared_gateup<<<dim3(I2 / 64, T / 128), 256>>>(x, wsg, wsu);
    k_final        <<<dim3(Hd / 128, T / 128), 256>>>(wsd, out);
}

// round 5
// speedup vs baseline: 1.5228x; 1.5228x over previous
#include <cuda_runtime.h>
#include <math.h>
#include <stdint.h>

// Problem constants (fixed by the reference setup)
#define T   2048
#define Hd  1024
#define Id  512
#define Ed  16
#define TK  6
#define TD  (T * TK)
#define I2  1024

// ---------------- scratch (static __device__, no allocations) ----------------
__device__ __align__(16) float g_act [TD * Id];
__device__ __align__(16) float g_ybuf[TD * Hd];
__device__ __align__(16) float g_sact[T  * I2];
__device__ float g_weight_tk[TD];
__device__ float g_row_w[TD];
__device__ int   g_expert_idx[TD];
__device__ int   g_row_token[TD];
__device__ int   g_pos[TD];
__device__ int   g_counts[Ed];
__device__ int   g_offsets[Ed];
__device__ int   g_cursors[Ed];

// ---------------------------------------------------------------------------
__device__ __forceinline__ uint32_t f2tf32(float f) {
    uint32_t r;
    asm("cvt.rna.tf32.f32 %0, %1;" : "=r"(r) : "f"(f));
    return r;
}

__device__ __forceinline__ void mma_m16n8k8(float* d, const uint32_t* a, const uint32_t* b) {
    asm volatile(
        "mma.sync.aligned.m16n8k8.row.col.f32.tf32.tf32.f32 "
        "{%0,%1,%2,%3}, {%4,%5,%6,%7}, {%8,%9}, {%0,%1,%2,%3};"
        : "+f"(d[0]), "+f"(d[1]), "+f"(d[2]), "+f"(d[3])
        : "r"(a[0]), "r"(a[1]), "r"(a[2]), "r"(a[3]), "r"(b[0]), "r"(b[1]));
}

__device__ __forceinline__ float silu(float g) { return g / (1.f + expf(-g)); }

// ---------------------------------------------------------------------------
__global__ void k_zero() {
    int i = threadIdx.x;
    if (i < Ed) g_counts[i] = 0;
}

__global__ void k_gate(const float* __restrict__ x,
                       const float* __restrict__ gw,
                       const float* __restrict__ gb) {
    int warp = threadIdx.x >> 5;
    int lane = threadIdx.x & 31;
    int t = blockIdx.x * 4 + warp;

    const float* xp = x + (size_t)t * Hd;
    float xr[32];
#pragma unroll
    for (int j = 0; j < 32; j++) xr[j] = xp[j * 32 + lane];

    __shared__ float ssc[4][Ed];
    for (int e = 0; e < Ed; e++) {
        const float* w = gw + (size_t)e * Hd;
        float s = 0.f;
#pragma unroll
        for (int j = 0; j < 32; j++) s += xr[j] * w[j * 32 + lane];
#pragma unroll
        for (int o = 16; o; o >>= 1) s += __shfl_xor_sync(0xffffffffu, s, o);
        if (lane == 0) ssc[warp][e] = 1.f / (1.f + expf(-s));
    }
    __syncwarp();

    if (lane == 0) {
        float sc[Ed], adj[Ed];
        for (int e = 0; e < Ed; e++) { sc[e] = ssc[warp][e]; adj[e] = sc[e] + gb[e]; }
        int   idx[TK];
        float w[TK];
        float sum = 0.f;
        for (int k = 0; k < TK; k++) {
            int   a  = 0;
            float mv = adj[0];
            for (int e = 1; e < Ed; e++) {
                if (adj[e] > mv) { mv = adj[e]; a = e; }   // first-max = jax tie-break
            }
            idx[k] = a;
            w[k]   = sc[a];
            sum   += w[k];
            adj[a] = -INFINITY;
        }
        float inv = 1.f / (sum + 1e-20f);
        for (int k = 0; k < TK; k++) {
            g_expert_idx[t * TK + k] = idx[k];
            g_weight_tk[t * TK + k]  = w[k] * inv;
            atomicAdd(&g_counts[idx[k]], 1);
        }
    }
}

__global__ void k_scan() {
    if (threadIdx.x == 0) {
        int o = 0;
        for (int e = 0; e < Ed; e++) {
            g_offsets[e] = o;
            g_cursors[e] = o;
            o += g_counts[e];
        }
    }
}

__global__ void k_scatter() {
    int i = blockIdx.x * blockDim.x + threadIdx.x;
    if (i < TD) {
        int e = g_expert_idx[i];
        int p = atomicAdd(&g_cursors[e], 1);
        g_row_token[p] = i / TK;
        g_row_w[p]     = g_weight_tk[i];
        g_pos[i]       = p;
    }
}

// ---------------------------------------------------------------------------
// Dual-output tf32 GEMM (gate+up) with SiLU epilogue.
// BM=128, BN=64 (per matrix), BK=32, 256 threads (8 warps).
// Warp layout: wy = warp&1 (2 x 64 rows), wx = warp>>1 (4 x 16 cols).
// Per warp: 4 m-frags x 2 n-frags x 2 matrices.
template<int LDB>
__device__ __forceinline__ void gemm_gateup_tf32(
    const float* __restrict__ abase, int lda, int gather,
    int cnt, int off, int m0, int n0,
    const float* __restrict__ Bg, const float* __restrict__ Bu,
    float* __restrict__ dst, int ldd, int K)
{
    __shared__ uint32_t As [32][132];
    __shared__ uint32_t Bgs[32][68];
    __shared__ uint32_t Bus[32][68];

    const int tid  = threadIdx.x;
    const int warp = tid >> 5, lane = tid & 31;
    const int wy = warp & 1, wx = warp >> 1;
    const int lr = lane >> 2, lk = lane & 3;

    // A loader: 4 float4/thread: c = tid + i*256, m = c&127, kq = c>>7 (0..7)
    const float* asrc[4];
#pragma unroll
    for (int i = 0; i < 4; i++) {
        int c = tid + i * 256;
        int m = c & 127, kq = c >> 7;
        int r = m0 + m;
        if (r < cnt) {
            int row = gather ? g_row_token[off + r] : r;
            asrc[i] = abase + (size_t)row * lda + kq * 4;
        } else asrc[i] = nullptr;
    }
    // B loader: 2 float4/thread/matrix: c = tid + i*256, br = c>>4 (0..31), bc = (c&15)*4
    const float* bgsrc[2];
    const float* busrc[2];
#pragma unroll
    for (int i = 0; i < 2; i++) {
        int c = tid + i * 256;
        int br = c >> 4, bc = (c & 15) << 2;
        bgsrc[i] = Bg + (size_t)br * LDB + n0 + bc;
        busrc[i] = Bu + (size_t)br * LDB + n0 + bc;
    }

    float accg[4][2][4] = {};
    float accu[4][2][4] = {};

    for (int k0 = 0; k0 < K; k0 += 32) {
#pragma unroll
        for (int i = 0; i < 4; i++) {
            int c = tid + i * 256;
            int m = c & 127, kq = c >> 7;
            float4 v = make_float4(0.f, 0.f, 0.f, 0.f);
            if (asrc[i]) v = *(const float4*)(asrc[i] + k0);
            As[kq * 4 + 0][m] = f2tf32(v.x);
            As[kq * 4 + 1][m] = f2tf32(v.y);
            As[kq * 4 + 2][m] = f2tf32(v.z);
            As[kq * 4 + 3][m] = f2tf32(v.w);
        }
#pragma unroll
        for (int i = 0; i < 2; i++) {
            int c = tid + i * 256;
            int br = c >> 4, bc = (c & 15) << 2;
            float4 vg = *(const float4*)(bgsrc[i] + (size_t)k0 * LDB);
            float4 vu = *(const float4*)(busrc[i] + (size_t)k0 * LDB);
            Bgs[br][bc + 0] = f2tf32(vg.x); Bgs[br][bc + 1] = f2tf32(vg.y);
            Bgs[br][bc + 2] = f2tf32(vg.z); Bgs[br][bc + 3] = f2tf32(vg.w);
            Bus[br][bc + 0] = f2tf32(vu.x); Bus[br][bc + 1] = f2tf32(vu.y);
            Bus[br][bc + 2] = f2tf32(vu.z); Bus[br][bc + 3] = f2tf32(vu.w);
        }
        __syncthreads();
#pragma unroll
        for (int kk = 0; kk < 32; kk += 8) {
            uint32_t a[4][4];
#pragma unroll
            for (int mf = 0; mf < 4; mf++) {
                int mb = wy * 64 + mf * 16 + lr;
                a[mf][0] = As[kk + lk][mb];
                a[mf][1] = As[kk + lk][mb + 8];
                a[mf][2] = As[kk + 4 + lk][mb];
                a[mf][3] = As[kk + 4 + lk][mb + 8];
            }
            uint32_t bg[2][2], bu[2][2];
#pragma unroll
            for (int nf = 0; nf < 2; nf++) {
                int nb = wx * 16 + nf * 8 + lr;
                bg[nf][0] = Bgs[kk + lk][nb];
                bg[nf][1] = Bgs[kk + 4 + lk][nb];
                bu[nf][0] = Bus[kk + lk][nb];
                bu[nf][1] = Bus[kk + 4 + lk][nb];
            }
#pragma unroll
            for (int mf = 0; mf < 4; mf++)
#pragma unroll
                for (int nf = 0; nf < 2; nf++) {
                    mma_m16n8k8(accg[mf][nf], a[mf], bg[nf]);
                    mma_m16n8k8(accu[mf][nf], a[mf], bu[nf]);
                }
        }
        __syncthreads();
    }

#pragma unroll
    for (int mf = 0; mf < 4; mf++)
#pragma unroll
        for (int nf = 0; nf < 2; nf++) {
            const float* cg = accg[mf][nf];
            const float* cu = accu[mf][nf];
            int r0 = m0 + wy * 64 + mf * 16 + lr;
            int n  = n0 + wx * 16 + nf * 8 + 2 * lk;
            if (r0 < cnt) {
                float2 v = make_float2(silu(cg[0]) * cu[0], silu(cg[1]) * cu[1]);
                *(float2*)(dst + (size_t)(off + r0) * ldd + n) = v;
            }
            int r1 = r0 + 8;
            if (r1 < cnt) {
                float2 v = make_float2(silu(cg[2]) * cu[2], silu(cg[3]) * cu[3]);
                *(float2*)(dst + (size_t)(off + r1) * ldd + n) = v;
            }
        }
}

__global__ void __launch_bounds__(256)
k_routed_gateup(const float* __restrict__ x,
                const float* __restrict__ wg,
                const float* __restrict__ wu) {
    const int e   = blockIdx.z;
    const int cnt = g_counts[e];
    const int m0  = blockIdx.y * 128;
    if (m0 >= cnt) return;
    gemm_gateup_tf32<Id>(x, Hd, 1, cnt, g_offsets[e], m0, blockIdx.x * 64,
                         wg + (size_t)e * Hd * Id, wu + (size_t)e * Hd * Id,
                         g_act, Id, Hd);
}

__global__ void __launch_bounds__(256)
k_shared_gateup(const float* __restrict__ x,
                const float* __restrict__ wsg,
                const float* __restrict__ wsu) {
    gemm_gateup_tf32<I2>(x, Hd, 0, T, 0, blockIdx.y * 128, blockIdx.x * 64,
                         wsg, wsu, g_sact, I2, Hd);
}

// ---------------------------------------------------------------------------
// Single-output tf32 GEMM: BM=128, BN=128, BK=32, 256 threads.
// Warp layout: wy = warp&1 (2 x 64 rows), wx = warp>>1 (4 x 32 cols).
// MODE 0: routed down (scale by g_row_w -> g_ybuf)
// MODE 1: shared down + combine (add sum_k ybuf -> out)
template<int MODE>
__device__ __forceinline__ void gemm_down_tf32(
    const float* __restrict__ abase, int lda,
    int cnt, int off, int m0, int n0,
    const float* __restrict__ B, int ldb, int K,
    float* __restrict__ dst, int ldd)
{
    __shared__ uint32_t As[32][132];
    __shared__ uint32_t Bs[32][132];

    const int tid  = threadIdx.x;
    const int warp = tid >> 5, lane = tid & 31;
    const int wy = warp & 1, wx = warp >> 1;
    const int lr = lane >> 2, lk = lane & 3;

    const float* asrc[4];
#pragma unroll
    for (int i = 0; i < 4; i++) {
        int c = tid + i * 256;
        int m = c & 127, kq = c >> 7;
        int r = m0 + m;
        asrc[i] = (r < cnt) ? abase + (size_t)(off + r) * lda + kq * 4 : nullptr;
    }
    const float* bsrc[4];
#pragma unroll
    for (int i = 0; i < 4; i++) {
        int c = tid + i * 256;
        int br = c >> 5, bc = (c & 31) << 2;
        bsrc[i] = B + (size_t)br * ldb + n0 + bc;
    }

    float acc[4][4][4] = {};

    for (int k0 = 0; k0 < K; k0 += 32) {
#pragma unroll
        for (int i = 0; i < 4; i++) {
            int c = tid + i * 256;
            int m = c & 127, kq = c >> 7;
            float4 v = make_float4(0.f, 0.f, 0.f, 0.f);
            if (asrc[i]) v = *(const float4*)(asrc[i] + k0);
            As[kq * 4 + 0][m] = f2tf32(v.x);
            As[kq * 4 + 1][m] = f2tf32(v.y);
            As[kq * 4 + 2][m] = f2tf32(v.z);
            As[kq * 4 + 3][m] = f2tf32(v.w);
        }
#pragma unroll
        for (int i = 0; i < 4; i++) {
            int c = tid + i * 256;
            int br = c >> 5, bc = (c & 31) << 2;
            float4 v = *(const float4*)(bsrc[i] + (size_t)k0 * ldb);
            Bs[br][bc + 0] = f2tf32(v.x); Bs[br][bc + 1] = f2tf32(v.y);
            Bs[br][bc + 2] = f2tf32(v.z); Bs[br][bc + 3] = f2tf32(v.w);
        }
        __syncthreads();
#pragma unroll
        for (int kk = 0; kk < 32; kk += 8) {
            uint32_t a[4][4];
#pragma unroll
            for (int mf = 0; mf < 4; mf++) {
                int mb = wy * 64 + mf * 16 + lr;
                a[mf][0] = As[kk + lk][mb];
                a[mf][1] = As[kk + lk][mb + 8];
                a[mf][2] = As[kk + 4 + lk][mb];
                a[mf][3] = As[kk + 4 + lk][mb + 8];
            }
            uint32_t b[4][2];
#pragma unroll
            for (int nf = 0; nf < 4; nf++) {
                int nb = wx * 32 + nf * 8 + lr;
                b[nf][0] = Bs[kk + lk][nb];
                b[nf][1] = Bs[kk + 4 + lk][nb];
            }
#pragma unroll
            for (int mf = 0; mf < 4; mf++)
#pragma unroll
                for (int nf = 0; nf < 4; nf++)
                    mma_m16n8k8(acc[mf][nf], a[mf], b[nf]);
        }
        __syncthreads();
    }

#pragma unroll
    for (int mf = 0; mf < 4; mf++) {
        int rb = m0 + wy * 64 + mf * 16 + lr;
#pragma unroll
        for (int half = 0; half < 2; half++) {
            int r = rb + half * 8;
            if (r >= cnt) continue;
            if (MODE == 0) {
                float w = g_row_w[off + r];
                float* d = dst + (size_t)(off + r) * ldd;
#pragma unroll
                for (int nf = 0; nf < 4; nf++) {
                    int n = n0 + wx * 32 + nf * 8 + 2 * lk;
                    float2 v = make_float2(acc[mf][nf][half * 2] * w,
                                           acc[mf][nf][half * 2 + 1] * w);
                    *(float2*)(d + n) = v;
                }
            } else {
                int pidx[TK];
#pragma unroll
                for (int k = 0; k < TK; k++) pidx[k] = g_pos[r * TK + k];
                float* d = dst + (size_t)r * ldd;
#pragma unroll
                for (int nf = 0; nf < 4; nf++) {
                    int n = n0 + wx * 32 + nf * 8 + 2 * lk;
                    float2 add = make_float2(0.f, 0.f);
#pragma unroll
                    for (int k = 0; k < TK; k++) {
                        float2 yb = *(const float2*)(g_ybuf + (size_t)pidx[k] * Hd + n);
                        add.x += yb.x; add.y += yb.y;
                    }
                    float2 v = make_float2(acc[mf][nf][half * 2] + add.x,
                                           acc[mf][nf][half * 2 + 1] + add.y);
                    *(float2*)(d + n) = v;
                }
            }
        }
    }
}

__global__ void __launch_bounds__(256)
k_routed_down(const float* __restrict__ wd) {
    const int e   = blockIdx.z;
    const int cnt = g_counts[e];
    const int m0  = blockIdx.y * 128;
    if (m0 >= cnt) return;
    gemm_down_tf32<0>(g_act, Id, cnt, g_offsets[e], m0, blockIdx.x * 128,
                      wd + (size_t)e * Id * Hd, Hd, Id, g_ybuf, Hd);
}

__global__ void __launch_bounds__(256)
k_final(const float* __restrict__ wsd, float* __restrict__ out) {
    gemm_down_tf32<1>(g_sact, I2, T, 0, blockIdx.y * 128, blockIdx.x * 128,
                      wsd, Hd, I2, out, Hd);
}

// ---------------------------------------------------------------------------
extern "C" void kernel_launch(void* const* d_in, const int* in_sizes, int n_in,
                              void* d_out, int out_size) {
    const float* x    = (const float*)d_in[0];
    const float* gw   = (const float*)d_in[1];
    const float* gb   = (const float*)d_in[2];
    const float* wg   = (const float*)d_in[3];
    const float* wu   = (const float*)d_in[4];
    const float* wd   = (const float*)d_in[5];
    const float* wsg  = (const float*)d_in[6];
    const float* wsu  = (const float*)d_in[7];
    const float* wsd  = (const float*)d_in[8];
    float* out = (float*)d_out;

    k_zero<<<1, 32>>>();
    k_gate<<<T / 4, 128>>>(x, gw, gb);
    k_scan<<<1, 32>>>();
    k_scatter<<<(TD + 255) / 256, 256>>>();

    k_routed_gateup<<<dim3(Id / 64, T / 128, Ed), 256>>>(x, wg, wu);
    k_routed_down  <<<dim3(Hd / 128, T / 128, Ed), 256>>>(wd);

    k_shared_gateup<<<dim3(I2 / 64, T / 128), 256>>>(x, wsg, wsu);
    k_final        <<<dim3(Hd / 128, T / 128), 256>>>(wsd, out);
}